// round 13
// baseline (speedup 1.0000x reference)
#include <cuda_runtime.h>

// Quaternion power unit — lane=token layout + 4-way chain ILP.
//   Warp = one out-pair x 32 tokens (one per lane). Weights/bias warp-uniform;
//   token data one conflict-free LDS.128 per channel. Packed f32x2 math,
//   MUFU-free polynomial sincos. FOUR independent accumulator chains
//   (16 channels each) merged in-order: P = C0 (x) C1 (x) C2 (x) C3.

#define CIN 64
#define COUT 128
#define TOK_PER_BLK 32
#define OPP_PER_BLK 8     // out-pairs per block (one per warp)
#define NTHREADS 256      // 8 warps

typedef unsigned long long u64;

__device__ __forceinline__ u64 pk2(float lo, float hi) {
    u64 r; asm("mov.b64 %0, {%1, %2};" : "=l"(r) : "f"(lo), "f"(hi)); return r;
}
__device__ __forceinline__ void up2(u64 v, float& lo, float& hi) {
    asm("mov.b64 {%0, %1}, %2;" : "=f"(lo), "=f"(hi) : "l"(v));
}
__device__ __forceinline__ u64 f2fma(u64 a, u64 b, u64 c) {
    u64 d; asm("fma.rn.f32x2 %0, %1, %2, %3;" : "=l"(d) : "l"(a), "l"(b), "l"(c)); return d;
}
__device__ __forceinline__ u64 f2mul(u64 a, u64 b) {
    u64 d; asm("mul.rn.f32x2 %0, %1, %2;" : "=l"(d) : "l"(a), "l"(b)); return d;
}

#define SGNC 0x8000000080000000ull

// acc = acc (x) q  (Hamilton, acc on the left)
__device__ __forceinline__ void ham(u64& ar, u64& ai, u64& aj, u64& ak,
                                    u64 qr, u64 qi, u64 qj, u64 qk) {
    u64 nr = f2fma(ar, qr, f2fma(ai, qi ^ SGNC, f2fma(aj, qj ^ SGNC, f2mul(ak, qk ^ SGNC))));
    u64 ni = f2fma(ar, qi, f2fma(ai, qr,        f2fma(aj, qk,        f2mul(ak, qj ^ SGNC))));
    u64 nj = f2fma(ar, qj, f2fma(ai, qk ^ SGNC, f2fma(aj, qr,        f2mul(ak, qi))));
    u64 nk = f2fma(ar, qk, f2fma(ai, qj,        f2fma(aj, qi ^ SGNC, f2mul(ak, qr))));
    ar = nr; ai = ni; aj = nj; ak = nk;
}

struct PolyC { u64 S1, S2, S3, C1, C2, C3, C4, ONE; };

// q from float4 token data {th,iv,jv,kv} + uniform weight pair + bias pair.
__device__ __forceinline__ void mkq(float4 d, u64 w2, u64 bias2, const PolyC& P,
                                    u64& qr, u64& qi, u64& qj, u64& qk) {
    u64 th = f2fma(w2, pk2(d.x, d.x), bias2);
    u64 y  = f2mul(th, th);
    u64 p  = f2fma(y, P.S3, P.S2);
    p      = f2fma(y, p, P.S1);
    p      = f2fma(y, p, P.ONE);
    u64 s2 = f2mul(th, p);
    u64 q  = f2fma(y, P.C4, P.C3);
    q      = f2fma(y, q, P.C2);
    q      = f2fma(y, q, P.C1);
    qr     = f2fma(y, q, P.ONE);
    qi = f2mul(pk2(d.y, d.y), s2);
    qj = f2mul(pk2(d.z, d.z), s2);
    qk = f2mul(pk2(d.w, d.w), s2);
}

__global__ __launch_bounds__(NTHREADS, 3)
void qpu_kernel(const float* __restrict__ x, const float* __restrict__ w,
                const float* __restrict__ bias, float* __restrict__ out,
                int n_tokens)
{
    // token data: tokv[c][tk] = {th, iv, jv, kv}; 33-slot pad -> conflict-free
    __shared__ __align__(16) float4 tokv[CIN][TOK_PER_BLK + 1];   // ~33.8 KB
    // weights: swt[warp][c] = {w[2op][c], w[2op+1][c]}  (warp-uniform reads)
    __shared__ __align__(16) u64 swt[OPP_PER_BLK][CIN];           // 4 KB

    const int tid  = threadIdx.x;
    const int lane = tid & 31;
    const int wp   = tid >> 5;

    const int tokBase = (blockIdx.x >> 3) * TOK_PER_BLK;
    const int opBase  = (blockIdx.x & 7) * OPP_PER_BLK;
    const int opair   = opBase + wp;

    // ---- stage weights: warp wp loads its own rows, coalesced ----
    {
        int c0 = lane, c1 = lane + 32;
        const float* w0 = w + (2 * opair) * CIN;
        const float* w1 = w + (2 * opair + 1) * CIN;
        swt[wp][c0] = pk2(w0[c0], w1[c0]);
        swt[wp][c1] = pk2(w0[c1], w1[c1]);
    }

    // ---- stage token data: 2048 (tk,c) entries, 8 per thread, coalesced ----
    for (int idx = tid; idx < TOK_PER_BLK * CIN; idx += NTHREADS) {
        int tk = idx >> 6;       // 0..31
        int c  = idx & 63;       // 0..63
        int token = tokBase + tk;
        if (token < n_tokens) {
            const float* xp = x + (size_t)token * (4 * CIN);
            float r = xp[c];
            float i = xp[CIN + c];
            float j = xp[2 * CIN + c];
            float k = xp[3 * CIN + c];
            float inv = rsqrtf(fmaf(i, i, fmaf(j, j, fmaf(k, k, 1e-12f))));
            const float CLAMP = (float)(1.0 - 1e-6);
            r = fminf(fmaxf(r, -CLAMP), CLAMP);
            tokv[c][tk] = make_float4(acosf(r), i * inv, j * inv, k * inv);
        }
    }
    __syncthreads();

    const int token = tokBase + lane;
    if (token >= n_tokens) return;

    PolyC P;
    P.S1 = pk2(-1.6666667e-1f, -1.6666667e-1f);
    P.S2 = pk2( 8.3333333e-3f,  8.3333333e-3f);
    P.S3 = pk2(-1.9841270e-4f, -1.9841270e-4f);
    P.C1 = pk2(-0.5f, -0.5f);
    P.C2 = pk2( 4.1666667e-2f,  4.1666667e-2f);
    P.C3 = pk2(-1.3888889e-3f, -1.3888889e-3f);
    P.C4 = pk2( 2.4801587e-5f,  2.4801587e-5f);
    P.ONE = pk2(1.0f, 1.0f);

    const u64 bias2 = ((const u64*)bias)[opair];   // warp-uniform

    // FOUR independent chains: Cn = channels [16n, 16n+16)
    u64 a0r = P.ONE, a0i = 0ull, a0j = 0ull, a0k = 0ull;
    u64 a1r = P.ONE, a1i = 0ull, a1j = 0ull, a1k = 0ull;
    u64 a2r = P.ONE, a2i = 0ull, a2j = 0ull, a2k = 0ull;
    u64 a3r = P.ONE, a3i = 0ull, a3j = 0ull, a3k = 0ull;

#pragma unroll 2
    for (int t = 0; t < 16; ++t) {
        float4 d0 = tokv[t][lane];
        float4 d1 = tokv[16 + t][lane];
        float4 d2 = tokv[32 + t][lane];
        float4 d3 = tokv[48 + t][lane];
        u64 w0 = swt[wp][t];
        u64 w1 = swt[wp][16 + t];
        u64 w2 = swt[wp][32 + t];
        u64 w3 = swt[wp][48 + t];

        u64 qr, qi, qj, qk;
        mkq(d0, w0, bias2, P, qr, qi, qj, qk);
        ham(a0r, a0i, a0j, a0k, qr, qi, qj, qk);

        mkq(d1, w1, bias2, P, qr, qi, qj, qk);
        ham(a1r, a1i, a1j, a1k, qr, qi, qj, qk);

        mkq(d2, w2, bias2, P, qr, qi, qj, qk);
        ham(a2r, a2i, a2j, a2k, qr, qi, qj, qk);

        mkq(d3, w3, bias2, P, qr, qi, qj, qk);
        ham(a3r, a3i, a3j, a3k, qr, qi, qj, qk);
    }

    // merge in order: P = ((C0 (x) C1) (x) (C2 (x) C3))
    ham(a0r, a0i, a0j, a0k, a1r, a1i, a1j, a1k);
    ham(a2r, a2i, a2j, a2k, a3r, a3i, a3j, a3k);
    ham(a0r, a0i, a0j, a0k, a2r, a2i, a2j, a2k);

    // ---- normalize + store (2 floats per component) ----
    u64 eps2 = pk2(1e-12f, 1e-12f);
    u64 n2 = f2fma(a0r, a0r, f2fma(a0i, a0i, f2fma(a0j, a0j, f2fma(a0k, a0k, eps2))));
    float n0, n1; up2(n2, n0, n1);
    u64 inv2 = pk2(rsqrtf(n0), rsqrtf(n1));

    u64 v0 = f2mul(a0r, inv2);
    u64 v1 = f2mul(a0i, inv2);
    u64 v2 = f2mul(a0j, inv2);
    u64 v3 = f2mul(a0k, inv2);

    float2* ob = (float2*)(out + (size_t)token * (4 * COUT));
    ob[opair]        = *(float2*)&v0;   // pr
    ob[64 + opair]   = *(float2*)&v1;   // pi
    ob[128 + opair]  = *(float2*)&v2;   // pj
    ob[192 + opair]  = *(float2*)&v3;   // pk
}

extern "C" void kernel_launch(void* const* d_in, const int* in_sizes, int n_in,
                              void* d_out, int out_size) {
    const float* x = (const float*)d_in[0];
    const float* w = (const float*)d_in[1];
    const float* b = (const float*)d_in[2];
    int tokens = in_sizes[0] / (4 * CIN);
    int tokBlocks = (tokens + TOK_PER_BLK - 1) / TOK_PER_BLK;
    int grid = tokBlocks * 8;   // 8 opair-groups of 8 (64 out-pairs total)
    qpu_kernel<<<grid, NTHREADS>>>(x, w, b, (float*)d_out, tokens);
}